// round 9
// baseline (speedup 1.0000x reference)
#include <cuda_runtime.h>
#include <cuda_fp16.h>

#define NN 10000
#define FI 256
#define FO 64
#define BM 128
#define BN 64
#define NSPLIT 7
#define RT 79          // ceil(NN/BM)
#define NT 157         // ceil(NN/BN)
#define LOG2E 1.4426950408889634f

// ---------------- device scratch (no allocation allowed) ----------------
__device__ float g_Wh[NN * FO];
__device__ __half g_WhT[(size_t)FO * NN];     // n-major fp16 Wh^T
__device__ float2 g_e1[NN];                   // (exp2(f1'), exp2(0.2 f1'))
__device__ float2 g_e2[NN];                   // (exp2(f2'), exp2(0.2 f2'))
__device__ float g_pacc[(size_t)NSPLIT * RT * BM * FO];
__device__ float g_pden[NSPLIT * RT * BM];

// ---------------- smem layout (bytes) ----------------
#define PSTB 144                      // B row stride: 128B + 16B pad (ldmatrix)
#define SM_E1 0                       // 128 float2
#define SM_E2 1024                    // 64 float2
#define SM_B  1536                    // 64 * 144
#define SM_TOTAL (SM_B + FO * PSTB)   // 10752

// ---------------- PTX helpers ----------------
__device__ __forceinline__ unsigned s2u(const void* p) {
    unsigned a;
    asm("{ .reg .u64 t; cvta.to.shared.u64 t, %1; cvt.u32.u64 %0, t; }"
        : "=r"(a) : "l"(p));
    return a;
}
__device__ __forceinline__ void ldsm4(unsigned* r, unsigned addr) {
    asm volatile("ldmatrix.sync.aligned.m8n8.x4.shared.b16 {%0,%1,%2,%3}, [%4];"
                 : "=r"(r[0]), "=r"(r[1]), "=r"(r[2]), "=r"(r[3]) : "r"(addr));
}
__device__ __forceinline__ void hmma(float* c, const unsigned* a, const unsigned* b) {
    asm volatile(
        "mma.sync.aligned.m16n8k16.row.col.f32.f16.f16.f32 "
        "{%0,%1,%2,%3}, {%4,%5,%6,%7}, {%8,%9}, {%0,%1,%2,%3};"
        : "+f"(c[0]), "+f"(c[1]), "+f"(c[2]), "+f"(c[3])
        : "r"(a[0]), "r"(a[1]), "r"(a[2]), "r"(a[3]), "r"(b[0]), "r"(b[1]));
}

// ---------------- Kernel 1: Wh = h @ W  (+ fp16 Wh^T) ----------------
__global__ __launch_bounds__(256) void wh_kernel(const float* __restrict__ h,
                                                 const float* __restrict__ W) {
    __shared__ float sh[16 * FI];
    int row0 = blockIdx.x * 16;
    const float* hp = h + (long long)row0 * FI;
    for (int t = threadIdx.x; t < 16 * FI; t += 256) sh[t] = hp[t];
    __syncthreads();
    int c = threadIdx.x & 63;
    int ty = threadIdx.x >> 6;
    float acc[4] = {0.f, 0.f, 0.f, 0.f};
    for (int k = 0; k < FI; ++k) {
        float w = W[k * FO + c];
        acc[0] += sh[(ty * 4 + 0) * FI + k] * w;
        acc[1] += sh[(ty * 4 + 1) * FI + k] * w;
        acc[2] += sh[(ty * 4 + 2) * FI + k] * w;
        acc[3] += sh[(ty * 4 + 3) * FI + k] * w;
    }
    __half hb[4];
    #pragma unroll
    for (int q = 0; q < 4; ++q) {
        int row = row0 + ty * 4 + q;
        g_Wh[row * FO + c] = acc[q];
        hb[q] = __float2half_rn(acc[q]);
    }
    size_t off = (size_t)c * NN + row0 + ty * 4;
    *(uint2*)&g_WhT[off] = *(uint2*)hb;
}

// ---------------- Kernel 2: f1/f2 -> exp2 pair tables ----------------
__global__ __launch_bounds__(128) void f12_kernel(const float* __restrict__ a) {
    int row = blockIdx.x * 4 + (threadIdx.x >> 5);
    int lane = threadIdx.x & 31;
    float w0 = g_Wh[row * FO + lane];
    float w1 = g_Wh[row * FO + 32 + lane];
    float s1 = w0 * a[lane] + w1 * a[lane + 32];
    float s2 = w0 * a[FO + lane] + w1 * a[FO + 32 + lane];
    #pragma unroll
    for (int o = 16; o > 0; o >>= 1) {
        s1 += __shfl_xor_sync(0xffffffffu, s1, o);
        s2 += __shfl_xor_sync(0xffffffffu, s2, o);
    }
    if (lane == 0) {
        s1 *= LOG2E; s2 *= LOG2E;
        g_e1[row] = make_float2(exp2f(s1), exp2f(0.2f * s1));
        g_e2[row] = make_float2(exp2f(s2), exp2f(0.2f * s2));
    }
}

// ------- Kernel 3: register-direct A-frag P-gen (ballot masks) + MMA ------
__global__ __launch_bounds__(256, 2) void gat_mma(const int* __restrict__ adj) {
    extern __shared__ char smem[];
    const unsigned sb = s2u(smem);
    float2* se1 = (float2*)(smem + SM_E1);
    float2* se2 = (float2*)(smem + SM_E2);

    const int tid = threadIdx.x, wid = tid >> 5, lane = tid & 31;
    const int half = lane >> 4, seg = lane & 15;
    const int q = lane & 3, r0 = lane >> 2;        // frag row base (0..7), col pair
    const int mt = blockIdx.x, jq = blockIdx.y;
    const int i0 = mt * BM;
    const int m0 = wid * 16;

    // coalesced adj map: load u -> lanes 0-15 row m0+2u (256B), 16-31 row +1
    const int rbase = i0 + m0 + half;
    const int* aptr = adj + (size_t)rbase * NN + seg * 4;

    // B-stage map
    const int bc = tid >> 2, bseg = tid & 3;

    // B fragment addressing (ldmatrix)
    const unsigned b_addr = sb + SM_B +
        ((lane & 7) + ((lane >> 4) & 1) * 8) * PSTB + ((lane >> 3) & 1) * 16;
    // ones-column B fragment for the denominator
    unsigned bd[2];
    bd[0] = bd[1] = (lane < 4) ? 0x3C003C00u : 0u;

    float acc[8][4], accD[4];
    #pragma unroll
    for (int nt = 0; nt < 8; ++nt)
        #pragma unroll
        for (int c = 0; c < 4; ++c) acc[nt][c] = 0.f;
    #pragma unroll
    for (int c = 0; c < 4; ++c) accD[c] = 0.f;

    // stage e1 once; rows are fixed per thread -> hoist to registers
    if (tid < BM) {
        int i = i0 + tid;
        se1[tid] = (i < NN) ? g_e1[i] : make_float2(0.f, 0.f);
    }
    __syncthreads();
    const float2 E0 = se1[m0 + r0];
    const float2 E1 = se1[m0 + r0 + 8];

    const int u0 = r0 >> 1;                           // 0..3
    const unsigned shift = 16 * (r0 & 1) + (q >> 1);  // pre-shift for bit tests
    const bool qodd = (q & 1) != 0;

    for (int t = jq; t < NT; t += NSPLIT) {
        const int j0 = t * BN;

        // ---- adj load + bit-space layout conversion ----
        const bool jok = (j0 + seg * 4 + 3) < NN;
        unsigned Ma0 = 0, Ma1 = 0, Mb0 = 0, Mb1 = 0;  // [row r0 / r0+8][col parity]
        #pragma unroll
        for (int u = 0; u < 8; ++u) {
            bool ok = jok && (rbase + 2 * u < NN);
            int4 mm = ok ? *(const int4*)(aptr + (size_t)(2 * u) * NN + j0)
                         : make_int4(0, 0, 0, 0);
            unsigned b0 = __ballot_sync(0xffffffffu, mm.x != 0);
            unsigned b1 = __ballot_sync(0xffffffffu, mm.y != 0);
            unsigned b2 = __ballot_sync(0xffffffffu, mm.z != 0);
            unsigned b3 = __ballot_sync(0xffffffffu, mm.w != 0);
            unsigned s0 = qodd ? b2 : b0;   // comp 2*(q&1)
            unsigned s1 = qodd ? b3 : b1;   // comp 2*(q&1)+1
            if (u < 4) { if (u == u0) { Ma0 = s0; Ma1 = s1; } }
            else       { if (u == u0 + 4) { Mb0 = s0; Mb1 = s1; } }
        }
        Ma0 >>= shift; Ma1 >>= shift; Mb0 >>= shift; Mb1 >>= shift;

        __syncthreads();   // previous tile's B/se2 reads complete

        // ---- stage B tile (WhT fp16) + e2 slice ----
        #pragma unroll
        for (int ch = 0; ch < 2; ++ch) {
            int e0 = bseg * 16 + ch * 8;
            uint4 v = make_uint4(0, 0, 0, 0);
            if (j0 + e0 + 7 < NN)
                v = *(const uint4*)(g_WhT + (size_t)bc * NN + j0 + e0);
            *(uint4*)(smem + SM_B + bc * PSTB + e0 * 2) = v;
        }
        if (tid < BN) {
            int j = j0 + tid;
            se2[tid] = (j < NN) ? g_e2[j] : make_float2(0.f, 0.f);
        }
        __syncthreads();

        // ---- per k-step: build A-frags in registers, ldsm B, HMMA ----
        #pragma unroll
        for (int ks = 0; ks < 4; ++ks) {
            const int cb = ks * 16 + 2 * q;
            float2 e00 = se2[cb], e01 = se2[cb + 1];
            float2 e10 = se2[cb + 8], e11 = se2[cb + 9];
            const unsigned k0 = 1u << (4 * ks), k2 = 1u << (4 * ks + 2);

            float pa0 = (Ma0 & k0) ? fmaxf(E0.x * e00.x, E0.y * e00.y) : 0.f;
            float pa1 = (Ma1 & k0) ? fmaxf(E0.x * e01.x, E0.y * e01.y) : 0.f;
            float pb0 = (Mb0 & k0) ? fmaxf(E1.x * e00.x, E1.y * e00.y) : 0.f;
            float pb1 = (Mb1 & k0) ? fmaxf(E1.x * e01.x, E1.y * e01.y) : 0.f;
            float pa2 = (Ma0 & k2) ? fmaxf(E0.x * e10.x, E0.y * e10.y) : 0.f;
            float pa3 = (Ma1 & k2) ? fmaxf(E0.x * e11.x, E0.y * e11.y) : 0.f;
            float pb2 = (Mb0 & k2) ? fmaxf(E1.x * e10.x, E1.y * e10.y) : 0.f;
            float pb3 = (Mb1 & k2) ? fmaxf(E1.x * e11.x, E1.y * e11.y) : 0.f;

            unsigned af[4];
            __half2 t0 = __floats2half2_rn(pa0, pa1); af[0] = *(unsigned*)&t0;
            __half2 t1 = __floats2half2_rn(pb0, pb1); af[1] = *(unsigned*)&t1;
            __half2 t2 = __floats2half2_rn(pa2, pa3); af[2] = *(unsigned*)&t2;
            __half2 t3 = __floats2half2_rn(pb2, pb3); af[3] = *(unsigned*)&t3;

            unsigned bfr[16];
            #pragma unroll
            for (int g = 0; g < 4; ++g)
                ldsm4(bfr + 4 * g, b_addr + g * 16 * PSTB + ks * 32);
            #pragma unroll
            for (int nt = 0; nt < 8; ++nt)
                hmma(acc[nt], af, bfr + nt * 2);
            hmma(accD, af, bd);
        }
    }

    // ---- epilogue ----
    {
        float* pa = g_pacc + (size_t)(jq * RT + mt) * BM * FO;
        int row = m0 + r0;
        int col = q * 2;
        #pragma unroll
        for (int nt = 0; nt < 8; ++nt) {
            *(float2*)&pa[row * FO + nt * 8 + col] = make_float2(acc[nt][0], acc[nt][1]);
            *(float2*)&pa[(row + 8) * FO + nt * 8 + col] = make_float2(acc[nt][2], acc[nt][3]);
        }
    }
    if (q == 0) {
        float* pd = g_pden + (jq * RT + mt) * BM;
        int row = m0 + r0;
        pd[row] = accD[0];
        pd[row + 8] = accD[2];
    }
}

// ---------------- Kernel 4: combine partials + ELU ----------------
__global__ __launch_bounds__(256) void combine_kernel(float* __restrict__ out) {
    int idx = blockIdx.x * 256 + threadIdx.x;
    if (idx >= NN * FO) return;
    int i = idx >> 6, c = idx & 63;
    int mt = i >> 7, row = i & 127;
    float a = 0.f, d = 0.f;
    #pragma unroll
    for (int q = 0; q < NSPLIT; ++q) {
        a += g_pacc[(size_t)(q * RT + mt) * BM * FO + row * FO + c];
        d += g_pden[(q * RT + mt) * BM + row];
    }
    float v = a / d;
    out[idx] = v > 0.f ? v : expm1f(v);
}

extern "C" void kernel_launch(void* const* d_in, const int* in_sizes, int n_in,
                              void* d_out, int out_size) {
    const float* h   = (const float*)d_in[0];
    const int*   adj = (const int*)d_in[1];
    const float* W   = (const float*)d_in[2];
    const float* a   = (const float*)d_in[3];
    float* out = (float*)d_out;

    wh_kernel<<<NN / 16, 256>>>(h, W);
    f12_kernel<<<NN / 4, 128>>>(a);
    gat_mma<<<dim3(RT, NSPLIT), 256, SM_TOTAL>>>(adj);
    combine_kernel<<<(NN * FO + 255) / 256, 256>>>(out);
}